// round 12
// baseline (speedup 1.0000x reference)
#include <cuda_runtime.h>
#include <cuda_fp16.h>

#define B 8
#define NPTS 2048
#define NPAIR (NPTS/2)
#define NTOT (B*NPTS)
#define NCHUNK 32            /* chunks per tile, 64 columns (32 pairs) each */
#define LOGW 7.6246189861593985f   /* ln(2048) */
#define LOG2E 1.4426950408889634f
#define LN2 0.6931471805599453f

typedef unsigned long long u64;

__device__ float4 d_X4[NTOT];              // sorted rows (x,y,z, 0.5|p|^2)
__device__ float4 d_Y4[NTOT];
__device__ float4 d_cA[2][NTOT/2];         // sorted pair-packed cols: (x0,x1,y0,y1)
__device__ float4 d_cB[2][NTOT/2];         // sorted pair-packed cols: (z0,z1,-w0,-w1)
__device__ float4 d_chunk[2*B][NCHUNK];    // per (b,cloud): centroid xyz + radius
__device__ float d_pots[2][4][NTOT];       // [buffer][f,g,fx,gy]
__device__ float d_mprev[4][NTOT];         // row-max estimate (= w - softmin_raw)

__device__ __forceinline__ float lg2(float x){ float r; asm("lg2.approx.f32 %0, %1;":"=f"(r):"f"(x)); return r; }
__device__ __forceinline__ u64 dup2(float x){ u64 r; asm("mov.b64 %0, {%1, %1};":"=l"(r):"f"(x)); return r; }
__device__ __forceinline__ u64 ffma2(u64 a, u64 b, u64 c){ u64 r; asm("fma.rn.f32x2 %0, %1, %2, %3;":"=l"(r):"l"(a),"l"(b),"l"(c)); return r; }
__device__ __forceinline__ u64 fadd2(u64 a, u64 b){ u64 r; asm("add.rn.f32x2 %0, %1, %2;":"=l"(r):"l"(a),"l"(b)); return r; }
__device__ __forceinline__ void unpk(u64 v, float& lo, float& hi){ asm("mov.b64 {%0, %1}, %2;":"=f"(lo),"=f"(hi):"l"(v)); }
__device__ __forceinline__ unsigned ex2h2(u64 u2){
    unsigned r;
    asm("{\n\t.reg .f32 lo, hi;\n\t.reg .b32 h;\n\t"
        "mov.b64 {lo, hi}, %1;\n\t"
        "cvt.rn.f16x2.f32 h, hi, lo;\n\t"
        "ex2.approx.f16x2 %0, h;\n\t}"
        : "=r"(r) : "l"(u2));
    return r;
}
__device__ __forceinline__ unsigned hadd2(unsigned a, unsigned b){
    unsigned r; asm("add.rn.f16x2 %0, %1, %2;":"=r"(r):"r"(a),"r"(b)); return r;
}
__device__ __forceinline__ u64 ex2pair(u64 a){
    u64 r;
    asm("{\n\t.reg .f32 lo, hi, el, eh;\n\t"
        "mov.b64 {lo, hi}, %1;\n\t"
        "ex2.approx.ftz.f32 el, lo;\n\t"
        "ex2.approx.ftz.f32 eh, hi;\n\t"
        "mov.b64 %0, {el, eh};\n\t}"
        : "=l"(r) : "l"(a));
    return r;
}

__device__ __forceinline__ int morton_key(float x, float y, float z) {
    int cx = min(7, max(0, (int)((x + 3.5f) * (8.0f / 7.0f))));
    int cy = min(7, max(0, (int)((y + 3.5f) * (8.0f / 7.0f))));
    int cz = min(7, max(0, (int)((z + 3.5f) * (8.0f / 7.0f))));
    int k = 0;
#pragma unroll
    for (int bit = 0; bit < 3; bit++) {
        k |= ((cx >> bit) & 1) << (3 * bit + 2);
        k |= ((cy >> bit) & 1) << (3 * bit + 1);
        k |= ((cz >> bit) & 1) << (3 * bit + 0);
    }
    return k;
}

// One block per (batch, cloud): Morton counting-sort 2048 points, emit sorted
// row/column arrays + chunk bounding spheres; zero potentials.
__global__ __launch_bounds__(256) void prep_kernel(const float* __restrict__ p1,
                                                   const float* __restrict__ p2) {
    __shared__ float4 spts[NPTS];     // 32KB sorted points
    __shared__ int hist[512];
    int b = blockIdx.x, cloud = blockIdx.y;
    const float* src = (cloud ? p2 : p1) + b * NPTS * 3;
    int tid = threadIdx.x;

    for (int i = tid; i < 512; i += 256) hist[i] = 0;
    __syncthreads();
    for (int i = tid; i < NPTS; i += 256) {
        float x = src[3*i], y = src[3*i+1], z = src[3*i+2];
        atomicAdd(&hist[morton_key(x, y, z)], 1);
    }
    __syncthreads();
    if (tid == 0) {
        int acc = 0;
        for (int c = 0; c < 512; c++) { int h = hist[c]; hist[c] = acc; acc += h; }
    }
    __syncthreads();
    for (int i = tid; i < NPTS; i += 256) {
        float x = src[3*i], y = src[3*i+1], z = src[3*i+2];
        int pos = atomicAdd(&hist[morton_key(x, y, z)], 1);
        spts[pos] = make_float4(x, y, z, 0.5f * (x*x + y*y + z*z));
    }
    __syncthreads();

    float4* dst = (cloud ? d_Y4 : d_X4) + b * NPTS;
    float4* cAo = d_cA[cloud] + b * NPAIR;
    float4* cBo = d_cB[cloud] + b * NPAIR;
    for (int i = tid; i < NPTS; i += 256) dst[i] = spts[i];
    for (int i = tid; i < NPAIR; i += 256) {
        float4 a = spts[2*i], q = spts[2*i + 1];
        cAo[i] = make_float4(a.x, q.x, a.y, q.y);
        cBo[i] = make_float4(a.z, q.z, -a.w, -q.w);
    }
    if (tid < NCHUNK) {
        float sx = 0.f, sy = 0.f, sz = 0.f;
        for (int j = 0; j < 64; j++) { float4 p = spts[tid*64 + j]; sx += p.x; sy += p.y; sz += p.z; }
        float cx = sx * (1.f/64.f), cy = sy * (1.f/64.f), cz = sz * (1.f/64.f);
        float r2 = 0.f;
        for (int j = 0; j < 64; j++) {
            float4 p = spts[tid*64 + j];
            float dx = p.x - cx, dy = p.y - cy, dz = p.z - cz;
            r2 = fmaxf(r2, dx*dx + dy*dy + dz*dz);
        }
        d_chunk[b*2 + cloud][tid] = make_float4(cx, cy, cz, sqrtf(r2) * 1.0001f + 1e-6f);
    }
    int t0 = cloud, t2 = cloud + 2;   // tasks whose rows live on this cloud
    for (int i = tid; i < NPTS; i += 256) {
        d_pots[0][t0][b*NPTS + i] = 0.f; d_pots[0][t2][b*NPTS + i] = 0.f;
        d_mprev[t0][b*NPTS + i] = 0.f;   d_mprev[t2][b*NPTS + i] = 0.f;
    }
}

#define RPW 4
#define WARPS 8
#define TPB (WARPS*32)  // 256
#define RPB (RPW*WARPS) // 32

// Single-pass softmin with prev-iteration max estimate.
// screen=1 (small eps): per-warp chunk screening — chunks provably below the
// f16 flush threshold (t < m - 17 eps) are skipped; identical-to-flush numerics.
__global__ __launch_bounds__(TPB) void iter_kernel(float eps, int inbuf, int avg,
                                                   int exact, int screen) {
    __shared__ float4 shA[NPAIR];
    __shared__ float4 shB[NPAIR];
    __shared__ float4 shC[NCHUNK];    // chunk centroid+radius (column cloud)
    __shared__ float  shP[NCHUNK];    // per-iter chunk potential bound P'_c
    int task = blockIdx.z, b = blockIdx.y;
    int ob = inbuf ^ 1;
    const float4* rows; const float4* cA; const float4* cB;
    const float* colpot; const float* rowold; float* outp;
    int colcloud;
    if (task == 0)      { rows = d_X4; cA = d_cA[1]; cB = d_cB[1]; colpot = d_pots[inbuf][1]; rowold = d_pots[inbuf][0]; outp = d_pots[ob][0]; colcloud = 1; }
    else if (task == 1) { rows = d_Y4; cA = d_cA[0]; cB = d_cB[0]; colpot = d_pots[inbuf][0]; rowold = d_pots[inbuf][1]; outp = d_pots[ob][1]; colcloud = 0; }
    else if (task == 2) { rows = d_X4; cA = d_cA[0]; cB = d_cB[0]; colpot = d_pots[inbuf][2]; rowold = d_pots[inbuf][2]; outp = d_pots[ob][2]; colcloud = 0; }
    else                { rows = d_Y4; cA = d_cA[1]; cB = d_cB[1]; colpot = d_pots[inbuf][3]; rowold = d_pots[inbuf][3]; outp = d_pots[ob][3]; colcloud = 1; }
    float* mprev = d_mprev[task] + b*NPTS;
    rows += b*NPTS; cA += b*NPAIR; cB += b*NPAIR; colpot += b*NPTS; rowold += b*NPTS; outp += b*NPTS;

    float eps_logw = eps * LOGW;
    for (int k = threadIdx.x; k < NPAIR; k += TPB) {
        shA[k] = cA[k];
        float4 zb = cB[k];
        float p0 = colpot[2*k], p1 = colpot[2*k+1];
        shB[k] = make_float4(zb.x, zb.y, p0 + zb.z - eps_logw, p1 + zb.w - eps_logw);
    }
    if (threadIdx.x < NCHUNK) shC[threadIdx.x] = d_chunk[b*2 + colcloud][threadIdx.x];
    __syncthreads();

    if (screen) {
        // P'_c = max_j (pot'_j + c_c . y_j), 8 threads per chunk
        int c = threadIdx.x >> 3, part = threadIdx.x & 7;
        float4 cc = shC[c];
        float pm = -3.4e38f;
#pragma unroll
        for (int j = 0; j < 4; j++) {
            int k = c*32 + part*4 + j;
            float4 a = shA[k]; float4 bq = shB[k];
            float t0v = bq.z + cc.x*a.x + cc.y*a.z + cc.z*bq.x;
            float t1v = bq.w + cc.x*a.y + cc.y*a.w + cc.z*bq.y;
            pm = fmaxf(pm, fmaxf(t0v, t1v));
        }
        pm = fmaxf(pm, __shfl_xor_sync(0xffffffffu, pm, 4));
        pm = fmaxf(pm, __shfl_xor_sync(0xffffffffu, pm, 2));
        pm = fmaxf(pm, __shfl_xor_sync(0xffffffffu, pm, 1));
        if (part == 0) shP[c] = pm;
        __syncthreads();
    }

    int warp = threadIdx.x >> 5, lane = threadIdx.x & 31;
    int row0 = blockIdx.x * RPB + warp * RPW;

    float kk = LOG2E / eps;
    u64 kk2 = dup2(kk);

    u64 rx2[RPW], ry2[RPW], rz2[RPW], mk2[RPW];
    float slo[RPW], shi[RPW];
#pragma unroll
    for (int r = 0; r < RPW; r++) {
        float4 xr = rows[row0 + r];
        rx2[r] = dup2(xr.x); ry2[r] = dup2(xr.y); rz2[r] = dup2(xr.z);
        mk2[r] = dup2(-mprev[row0 + r] * kk);
        slo[r] = 0.f; shi[r] = 0.f;
    }

    const ulonglong2* sA = (const ulonglong2*)shA;
    const ulonglong2* sB = (const ulonglong2*)shB;

    if (exact) {
        // exact f32 exp path (final extrapolation)
#pragma unroll 4
        for (int k = lane; k < NPAIR; k += 32) {
            ulonglong2 ab = sA[k];
            ulonglong2 zw = sB[k];
#pragma unroll
            for (int r = 0; r < RPW; r++) {
                u64 t2 = ffma2(rz2[r], zw.x, zw.y);
                t2 = ffma2(ry2[r], ab.y, t2);
                t2 = ffma2(rx2[r], ab.x, t2);
                u64 e2 = ex2pair(ffma2(t2, kk2, mk2[r]));
                float lo, hi; unpk(e2, lo, hi);
                slo[r] += lo; shi[r] += hi;
            }
        }
    } else if (screen) {
        // build active-chunk mask: bound_c = P'_c + (x-c).c + |x-c| r_c
        unsigned amask;
        {
            float4 cc = shC[lane];
            float Pp = shP[lane];
            bool act = false;
#pragma unroll
            for (int r = 0; r < RPW; r++) {
                float4 xr = rows[row0 + r];
                float thr = mprev[row0 + r] - 17.0f * eps;
                float dx = xr.x - cc.x, dy = xr.y - cc.y, dz = xr.z - cc.z;
                float d2 = dx*dx + dy*dy + dz*dz;
                float bnd = Pp + dx*cc.x + dy*cc.y + dz*cc.z + sqrtf(d2) * cc.w;
                act |= (bnd >= thr);
            }
            amask = __ballot_sync(0xffffffffu, act);
        }
        unsigned hacc[RPW];
#pragma unroll
        for (int r = 0; r < RPW; r++) hacc[r] = 0u;
        int cnt = 0;
        unsigned mm = amask;
        while (mm) {
            int c = __ffs(mm) - 1; mm &= mm - 1;
            int k = (c << 5) + lane;
            ulonglong2 ab = sA[k];
            ulonglong2 zw = sB[k];
#pragma unroll
            for (int r = 0; r < RPW; r++) {
                u64 t2 = ffma2(rz2[r], zw.x, zw.y);
                t2 = ffma2(ry2[r], ab.y, t2);
                t2 = ffma2(rx2[r], ab.x, t2);
                hacc[r] = hadd2(hacc[r], ex2h2(ffma2(t2, kk2, mk2[r])));
            }
            if (((++cnt) & 7) == 0) {
#pragma unroll
                for (int r = 0; r < RPW; r++) {
                    float2 f = __half22float2(*(const __half2*)&hacc[r]);
                    slo[r] += f.x; shi[r] += f.y;
                    hacc[r] = 0u;
                }
            }
        }
#pragma unroll
        for (int r = 0; r < RPW; r++) {
            float2 f = __half22float2(*(const __half2*)&hacc[r]);
            slo[r] += f.x; shi[r] += f.y;
        }
    } else {
        // dense f16x2 exp path
#pragma unroll 1
        for (int kb = 0; kb < NPAIR; kb += 256) {
            unsigned hacc[RPW];
#pragma unroll
            for (int r = 0; r < RPW; r++) hacc[r] = 0u;
#pragma unroll
            for (int kc = 0; kc < 8; kc++) {
                int k = kb + kc * 32 + lane;
                ulonglong2 ab = sA[k];
                ulonglong2 zw = sB[k];
#pragma unroll
                for (int r = 0; r < RPW; r++) {
                    u64 t2 = ffma2(rz2[r], zw.x, zw.y);
                    t2 = ffma2(ry2[r], ab.y, t2);
                    t2 = ffma2(rx2[r], ab.x, t2);
                    hacc[r] = hadd2(hacc[r], ex2h2(ffma2(t2, kk2, mk2[r])));
                }
            }
#pragma unroll
            for (int r = 0; r < RPW; r++) {
                float2 f = __half22float2(*(const __half2*)&hacc[r]);
                slo[r] += f.x; shi[r] += f.y;
            }
        }
    }

    float s[RPW];
#pragma unroll
    for (int r = 0; r < RPW; r++) s[r] = slo[r] + shi[r];
#pragma unroll
    for (int off = 16; off; off >>= 1)
#pragma unroll
        for (int r = 0; r < RPW; r++)
            s[r] += __shfl_xor_sync(0xffffffffu, s[r], off);

    float m_used[RPW];
#pragma unroll
    for (int r = 0; r < RPW; r++) m_used[r] = mprev[row0 + r];

    // safety net: recompute max + full unscreened f32 resum (cold)
    unsigned badmask = 0;
#pragma unroll
    for (int r = 0; r < RPW; r++)
        if (!(s[r] >= 1e-12f && s[r] <= 1e30f)) badmask |= 1u << r;
    if (__any_sync(0xffffffffu, badmask != 0)) {
        float mlo[RPW], mhi[RPW];
#pragma unroll
        for (int r = 0; r < RPW; r++) { mlo[r] = -3.4e38f; mhi[r] = -3.4e38f; }
        for (int k = lane; k < NPAIR; k += 32) {
            ulonglong2 ab = sA[k];
            ulonglong2 zw = sB[k];
#pragma unroll
            for (int r = 0; r < RPW; r++) {
                u64 t2 = ffma2(rz2[r], zw.x, zw.y);
                t2 = ffma2(ry2[r], ab.y, t2);
                t2 = ffma2(rx2[r], ab.x, t2);
                float lo, hi; unpk(t2, lo, hi);
                mlo[r] = fmaxf(mlo[r], lo);
                mhi[r] = fmaxf(mhi[r], hi);
            }
        }
        float mt[RPW];
#pragma unroll
        for (int r = 0; r < RPW; r++) mt[r] = fmaxf(mlo[r], mhi[r]);
#pragma unroll
        for (int off = 16; off; off >>= 1)
#pragma unroll
            for (int r = 0; r < RPW; r++)
                mt[r] = fmaxf(mt[r], __shfl_xor_sync(0xffffffffu, mt[r], off));
        u64 sb2[RPW], mkb[RPW];
#pragma unroll
        for (int r = 0; r < RPW; r++) { mkb[r] = dup2(-mt[r] * kk); sb2[r] = 0; }
        for (int k = lane; k < NPAIR; k += 32) {
            ulonglong2 ab = sA[k];
            ulonglong2 zw = sB[k];
#pragma unroll
            for (int r = 0; r < RPW; r++) {
                u64 t2 = ffma2(rz2[r], zw.x, zw.y);
                t2 = ffma2(ry2[r], ab.y, t2);
                t2 = ffma2(rx2[r], ab.x, t2);
                sb2[r] = fadd2(sb2[r], ex2pair(ffma2(t2, kk2, mkb[r])));
            }
        }
        float sn[RPW];
#pragma unroll
        for (int r = 0; r < RPW; r++) { float lo, hi; unpk(sb2[r], lo, hi); sn[r] = lo + hi; }
#pragma unroll
        for (int off = 16; off; off >>= 1)
#pragma unroll
            for (int r = 0; r < RPW; r++)
                sn[r] += __shfl_xor_sync(0xffffffffu, sn[r], off);
#pragma unroll
        for (int r = 0; r < RPW; r++)
            if ((badmask >> r) & 1u) { s[r] = sn[r]; m_used[r] = mt[r]; }
    }

    if (lane < RPW) {
        int r = lane;
        int row = row0 + r;
        float rww = rows[row].w;
        float sm = rww - m_used[r] - eps * (lg2(s[r]) * LN2);
        outp[row] = avg ? 0.5f * (rowold[row] + sm) : sm;
        mprev[row] = rww - sm;
    }
}

__global__ void reduce_kernel(int buf, float* __restrict__ out) {
    __shared__ float red[256];
    float acc = 0.f;
    for (int i = threadIdx.x; i < NTOT; i += 256) {
        acc += (d_pots[buf][0][i] - d_pots[buf][2][i])
             + (d_pots[buf][1][i] - d_pots[buf][3][i]);
    }
    red[threadIdx.x] = acc;
    __syncthreads();
    for (int off = 128; off; off >>= 1) {
        if (threadIdx.x < off) red[threadIdx.x] += red[threadIdx.x + off];
        __syncthreads();
    }
    if (threadIdx.x == 0) out[0] = red[0] / (float)NTOT;
}

extern "C" void kernel_launch(void* const* d_in, const int* in_sizes, int n_in,
                              void* d_out, int out_size) {
    const float* p1 = (const float*)d_in[0];
    const float* p2 = (const float*)d_in[1];
    float* out = (float*)d_out;

    float eps[128]; int n = 0;
    double sc = 8.0;
    while (sc > 0.01 && n < 120) { float f = (float)sc; eps[n++] = f * f; sc *= 0.9; }
    { float f = 0.01f; eps[n++] = f * f; }

    prep_kernel<<<dim3(B, 2), 256>>>(p1, p2);

    int inbuf = 0;
    dim3 grid(NPTS / RPB, B, 4);
    for (int k = 0; k < n; k++) {
        int screen = (eps[k] <= 0.05f) ? 1 : 0;
        iter_kernel<<<grid, TPB>>>(eps[k], inbuf, 1, 0, screen);
        inbuf ^= 1;
    }
    // final extrapolation: exact f32 exp, unscreened, no averaging
    iter_kernel<<<grid, TPB>>>(eps[n - 1], inbuf, 0, 1, 0);
    reduce_kernel<<<1, 256>>>(inbuf ^ 1, out);
}

// round 13
// speedup vs baseline: 1.0415x; 1.0415x over previous
#include <cuda_runtime.h>
#include <cuda_fp16.h>

#define B 8
#define NPTS 2048
#define NPAIR (NPTS/2)
#define NTOT (B*NPTS)
#define NCHUNK 32            /* 32 chunks x 64 sorted points (32 pairs) */
#define LOGW 7.6246189861593985f
#define LOG2E 1.4426950408889634f
#define LN2 0.6931471805599453f

typedef unsigned long long u64;

__device__ float4 d_X4[NTOT];              // sorted rows (x,y,z, 0.5|p|^2)
__device__ float4 d_Y4[NTOT];
__device__ float4 d_cA[2][NTOT/2];         // sorted pair-packed cols: (x0,x1,y0,y1)
__device__ float4 d_cB[2][NTOT/2];         // sorted pair-packed cols: (z0,z1,-w0,-w1)
__device__ float d_chunkY[2*B][NCHUNK];    // per (b,cloud): max |y| per chunk
__device__ float d_pots[2][4][NTOT];
__device__ float d_mprev[4][NTOT];

__device__ __forceinline__ float lg2(float x){ float r; asm("lg2.approx.f32 %0, %1;":"=f"(r):"f"(x)); return r; }
__device__ __forceinline__ u64 dup2(float x){ u64 r; asm("mov.b64 %0, {%1, %1};":"=l"(r):"f"(x)); return r; }
__device__ __forceinline__ u64 ffma2(u64 a, u64 b, u64 c){ u64 r; asm("fma.rn.f32x2 %0, %1, %2, %3;":"=l"(r):"l"(a),"l"(b),"l"(c)); return r; }
__device__ __forceinline__ u64 fadd2(u64 a, u64 b){ u64 r; asm("add.rn.f32x2 %0, %1, %2;":"=l"(r):"l"(a),"l"(b)); return r; }
__device__ __forceinline__ void unpk(u64 v, float& lo, float& hi){ asm("mov.b64 {%0, %1}, %2;":"=f"(lo),"=f"(hi):"l"(v)); }
__device__ __forceinline__ unsigned ex2h2(u64 u2){
    unsigned r;
    asm("{\n\t.reg .f32 lo, hi;\n\t.reg .b32 h;\n\t"
        "mov.b64 {lo, hi}, %1;\n\t"
        "cvt.rn.f16x2.f32 h, hi, lo;\n\t"
        "ex2.approx.f16x2 %0, h;\n\t}"
        : "=r"(r) : "l"(u2));
    return r;
}
__device__ __forceinline__ unsigned hadd2(unsigned a, unsigned b){
    unsigned r; asm("add.rn.f16x2 %0, %1, %2;":"=r"(r):"r"(a),"r"(b)); return r;
}
__device__ __forceinline__ u64 ex2pair(u64 a){
    u64 r;
    asm("{\n\t.reg .f32 lo, hi, el, eh;\n\t"
        "mov.b64 {lo, hi}, %1;\n\t"
        "ex2.approx.ftz.f32 el, lo;\n\t"
        "ex2.approx.ftz.f32 eh, hi;\n\t"
        "mov.b64 %0, {el, eh};\n\t}"
        : "=l"(r) : "l"(a));
    return r;
}

__device__ __forceinline__ int morton_key(float x, float y, float z) {
    int cx = min(7, max(0, (int)((x + 3.5f) * (8.0f / 7.0f))));
    int cy = min(7, max(0, (int)((y + 3.5f) * (8.0f / 7.0f))));
    int cz = min(7, max(0, (int)((z + 3.5f) * (8.0f / 7.0f))));
    int k = 0;
#pragma unroll
    for (int bit = 0; bit < 3; bit++) {
        k |= ((cx >> bit) & 1) << (3 * bit + 2);
        k |= ((cy >> bit) & 1) << (3 * bit + 1);
        k |= ((cz >> bit) & 1) << (3 * bit + 0);
    }
    return k;
}

__global__ __launch_bounds__(256) void prep_kernel(const float* __restrict__ p1,
                                                   const float* __restrict__ p2) {
    __shared__ float4 spts[NPTS];
    __shared__ int hist[512];
    int b = blockIdx.x, cloud = blockIdx.y;
    const float* src = (cloud ? p2 : p1) + b * NPTS * 3;
    int tid = threadIdx.x;

    for (int i = tid; i < 512; i += 256) hist[i] = 0;
    __syncthreads();
    for (int i = tid; i < NPTS; i += 256) {
        float x = src[3*i], y = src[3*i+1], z = src[3*i+2];
        atomicAdd(&hist[morton_key(x, y, z)], 1);
    }
    __syncthreads();
    if (tid == 0) {
        int acc = 0;
        for (int c = 0; c < 512; c++) { int h = hist[c]; hist[c] = acc; acc += h; }
    }
    __syncthreads();
    for (int i = tid; i < NPTS; i += 256) {
        float x = src[3*i], y = src[3*i+1], z = src[3*i+2];
        int pos = atomicAdd(&hist[morton_key(x, y, z)], 1);
        spts[pos] = make_float4(x, y, z, 0.5f * (x*x + y*y + z*z));
    }
    __syncthreads();

    float4* dst = (cloud ? d_Y4 : d_X4) + b * NPTS;
    float4* cAo = d_cA[cloud] + b * NPAIR;
    float4* cBo = d_cB[cloud] + b * NPAIR;
    for (int i = tid; i < NPTS; i += 256) dst[i] = spts[i];
    for (int i = tid; i < NPAIR; i += 256) {
        float4 a = spts[2*i], q = spts[2*i + 1];
        cAo[i] = make_float4(a.x, q.x, a.y, q.y);
        cBo[i] = make_float4(a.z, q.z, -a.w, -q.w);
    }
    if (tid < NCHUNK) {
        float m2 = 0.f;
        for (int j = 0; j < 64; j++) {
            float4 p = spts[tid*64 + j];
            m2 = fmaxf(m2, p.x*p.x + p.y*p.y + p.z*p.z);
        }
        d_chunkY[b*2 + cloud][tid] = sqrtf(m2) * 1.0001f + 1e-6f;
    }
    int t0 = cloud, t2 = cloud + 2;
    for (int i = tid; i < NPTS; i += 256) {
        d_pots[0][t0][b*NPTS + i] = 0.f; d_pots[0][t2][b*NPTS + i] = 0.f;
        d_mprev[t0][b*NPTS + i] = 0.f;   d_mprev[t2][b*NPTS + i] = 0.f;
    }
}

#define RPW 4
#define WARPS 8
#define TPB (WARPS*32)  // 256
#define RPB (RPW*WARPS) // 32

// Single-pass softmin; screen=1: chunks provably below the f16 flush line
// (t < m - 17 eps, exact chunk support at the block row-centroid + Lipschitz
// transfer) are skipped — numerically identical to the dense f16 flush.
__global__ __launch_bounds__(TPB) void iter_kernel(float eps, int inbuf, int avg,
                                                   int exact, int screen) {
    __shared__ float4 shA[NPAIR];
    __shared__ float4 shB[NPAIR];
    __shared__ float  shY[NCHUNK];     // max |y| per chunk
    __shared__ float  shP[NCHUNK];     // chunk bound at block centroid (+slack)
    __shared__ float4 shCent;          // block row centroid + dmax
    __shared__ int    shList[WARPS][NCHUNK];
    int task = blockIdx.z, b = blockIdx.y;
    int ob = inbuf ^ 1;
    const float4* rows; const float4* cA; const float4* cB;
    const float* colpot; const float* rowold; float* outp;
    int colcloud;
    if (task == 0)      { rows = d_X4; cA = d_cA[1]; cB = d_cB[1]; colpot = d_pots[inbuf][1]; rowold = d_pots[inbuf][0]; outp = d_pots[ob][0]; colcloud = 1; }
    else if (task == 1) { rows = d_Y4; cA = d_cA[0]; cB = d_cB[0]; colpot = d_pots[inbuf][0]; rowold = d_pots[inbuf][1]; outp = d_pots[ob][1]; colcloud = 0; }
    else if (task == 2) { rows = d_X4; cA = d_cA[0]; cB = d_cB[0]; colpot = d_pots[inbuf][2]; rowold = d_pots[inbuf][2]; outp = d_pots[ob][2]; colcloud = 0; }
    else                { rows = d_Y4; cA = d_cA[1]; cB = d_cB[1]; colpot = d_pots[inbuf][3]; rowold = d_pots[inbuf][3]; outp = d_pots[ob][3]; colcloud = 1; }
    float* mprev = d_mprev[task] + b*NPTS;
    rows += b*NPTS; cA += b*NPAIR; cB += b*NPAIR; colpot += b*NPTS; rowold += b*NPTS; outp += b*NPTS;

    float eps_logw = eps * LOGW;
    for (int k = threadIdx.x; k < NPAIR; k += TPB) {
        shA[k] = cA[k];
        float4 zb = cB[k];
        float p0 = colpot[2*k], p1 = colpot[2*k+1];
        shB[k] = make_float4(zb.x, zb.y, p0 + zb.z - eps_logw, p1 + zb.w - eps_logw);
    }
    if (screen) {
        if (threadIdx.x < NCHUNK) shY[threadIdx.x] = d_chunkY[b*2 + colcloud][threadIdx.x];
        if (threadIdx.x < 32) {
            // block row centroid + max distance (rows are Morton-local)
            float4 rr = rows[blockIdx.x * RPB + threadIdx.x];
            float sx = rr.x, sy = rr.y, sz = rr.z;
#pragma unroll
            for (int off = 16; off; off >>= 1) {
                sx += __shfl_xor_sync(0xffffffffu, sx, off);
                sy += __shfl_xor_sync(0xffffffffu, sy, off);
                sz += __shfl_xor_sync(0xffffffffu, sz, off);
            }
            float cx = sx * (1.f/32.f), cy = sy * (1.f/32.f), cz = sz * (1.f/32.f);
            float dx = rr.x - cx, dy = rr.y - cy, dz = rr.z - cz;
            float d2 = dx*dx + dy*dy + dz*dz;
#pragma unroll
            for (int off = 16; off; off >>= 1)
                d2 = fmaxf(d2, __shfl_xor_sync(0xffffffffu, d2, off));
            if (threadIdx.x == 0)
                shCent = make_float4(cx, cy, cz, sqrtf(d2) * 1.0001f + 1e-6f);
        }
    }
    __syncthreads();

    if (screen) {
        // exact chunk support at centroid: g_c = max_j (w'_j + xbar.y_j)
        // 8 threads/chunk, conflict-free striding (pair = part + 8j)
        int c = threadIdx.x >> 3, part = threadIdx.x & 7;
        float cx = shCent.x, cy = shCent.y, cz = shCent.z;
        float g = -3.4e38f;
#pragma unroll
        for (int j = 0; j < 4; j++) {
            int k = c*32 + part + 8*j;
            float4 a = shA[k]; float4 q = shB[k];
            float t0v = q.z + cx*a.x + cy*a.z + cz*q.x;
            float t1v = q.w + cx*a.y + cy*a.w + cz*q.y;
            g = fmaxf(g, fmaxf(t0v, t1v));
        }
        g = fmaxf(g, __shfl_xor_sync(0xffffffffu, g, 4));
        g = fmaxf(g, __shfl_xor_sync(0xffffffffu, g, 2));
        g = fmaxf(g, __shfl_xor_sync(0xffffffffu, g, 1));
        if (part == 0) shP[c] = g + shCent.w * shY[c];
        __syncthreads();
    }

    int warp = threadIdx.x >> 5, lane = threadIdx.x & 31;
    int row0 = blockIdx.x * RPB + warp * RPW;

    float kk = LOG2E / eps;
    u64 kk2 = dup2(kk);

    u64 rx2[RPW], ry2[RPW], rz2[RPW], mk2[RPW];
    float slo[RPW], shi[RPW];
#pragma unroll
    for (int r = 0; r < RPW; r++) {
        float4 xr = rows[row0 + r];
        rx2[r] = dup2(xr.x); ry2[r] = dup2(xr.y); rz2[r] = dup2(xr.z);
        mk2[r] = dup2(-mprev[row0 + r] * kk);
        slo[r] = 0.f; shi[r] = 0.f;
    }

    const ulonglong2* sA = (const ulonglong2*)shA;
    const ulonglong2* sB = (const ulonglong2*)shB;

    if (exact) {
#pragma unroll 4
        for (int k = lane; k < NPAIR; k += 32) {
            ulonglong2 ab = sA[k];
            ulonglong2 zw = sB[k];
#pragma unroll
            for (int r = 0; r < RPW; r++) {
                u64 t2 = ffma2(rz2[r], zw.x, zw.y);
                t2 = ffma2(ry2[r], ab.y, t2);
                t2 = ffma2(rx2[r], ab.x, t2);
                u64 e2 = ex2pair(ffma2(t2, kk2, mk2[r]));
                float lo, hi; unpk(e2, lo, hi);
                slo[r] += lo; shi[r] += hi;
            }
        }
    } else if (screen) {
        // warp threshold: skip chunk only if below EVERY row's flush line
        float thr = 3.4e38f;
#pragma unroll
        for (int r = 0; r < RPW; r++) thr = fminf(thr, mprev[row0 + r]);
        thr -= 17.0f * eps;
        bool act = (shP[lane] >= thr);
        unsigned amask = __ballot_sync(0xffffffffu, act);
        int cnt = __popc(amask);
        int idx = __popc(amask & ((1u << lane) - 1u));
        if (act) shList[warp][idx] = lane;
        __syncwarp();

        unsigned hacc[RPW];
#pragma unroll
        for (int r = 0; r < RPW; r++) hacc[r] = 0u;
#pragma unroll 2
        for (int i = 0; i < cnt; i++) {
            int c = shList[warp][i];
            int k = (c << 5) + lane;
            ulonglong2 ab = sA[k];
            ulonglong2 zw = sB[k];
#pragma unroll
            for (int r = 0; r < RPW; r++) {
                u64 t2 = ffma2(rz2[r], zw.x, zw.y);
                t2 = ffma2(ry2[r], ab.y, t2);
                t2 = ffma2(rx2[r], ab.x, t2);
                hacc[r] = hadd2(hacc[r], ex2h2(ffma2(t2, kk2, mk2[r])));
            }
            if ((i & 7) == 7) {
#pragma unroll
                for (int r = 0; r < RPW; r++) {
                    float2 f = __half22float2(*(const __half2*)&hacc[r]);
                    slo[r] += f.x; shi[r] += f.y;
                    hacc[r] = 0u;
                }
            }
        }
#pragma unroll
        for (int r = 0; r < RPW; r++) {
            float2 f = __half22float2(*(const __half2*)&hacc[r]);
            slo[r] += f.x; shi[r] += f.y;
        }
    } else {
        // dense f16x2 path (unchanged from R10)
#pragma unroll 1
        for (int kb = 0; kb < NPAIR; kb += 256) {
            unsigned hacc[RPW];
#pragma unroll
            for (int r = 0; r < RPW; r++) hacc[r] = 0u;
#pragma unroll
            for (int kc = 0; kc < 8; kc++) {
                int k = kb + kc * 32 + lane;
                ulonglong2 ab = sA[k];
                ulonglong2 zw = sB[k];
#pragma unroll
                for (int r = 0; r < RPW; r++) {
                    u64 t2 = ffma2(rz2[r], zw.x, zw.y);
                    t2 = ffma2(ry2[r], ab.y, t2);
                    t2 = ffma2(rx2[r], ab.x, t2);
                    hacc[r] = hadd2(hacc[r], ex2h2(ffma2(t2, kk2, mk2[r])));
                }
            }
#pragma unroll
            for (int r = 0; r < RPW; r++) {
                float2 f = __half22float2(*(const __half2*)&hacc[r]);
                slo[r] += f.x; shi[r] += f.y;
            }
        }
    }

    float s[RPW];
#pragma unroll
    for (int r = 0; r < RPW; r++) s[r] = slo[r] + shi[r];
#pragma unroll
    for (int off = 16; off; off >>= 1)
#pragma unroll
        for (int r = 0; r < RPW; r++)
            s[r] += __shfl_xor_sync(0xffffffffu, s[r], off);

    float m_used[RPW];
#pragma unroll
    for (int r = 0; r < RPW; r++) m_used[r] = mprev[row0 + r];

    // safety net: recompute max + full unscreened f32 resum (cold)
    unsigned badmask = 0;
#pragma unroll
    for (int r = 0; r < RPW; r++)
        if (!(s[r] >= 1e-12f && s[r] <= 1e30f)) badmask |= 1u << r;
    if (__any_sync(0xffffffffu, badmask != 0)) {
        float mlo[RPW], mhi[RPW];
#pragma unroll
        for (int r = 0; r < RPW; r++) { mlo[r] = -3.4e38f; mhi[r] = -3.4e38f; }
        for (int k = lane; k < NPAIR; k += 32) {
            ulonglong2 ab = sA[k];
            ulonglong2 zw = sB[k];
#pragma unroll
            for (int r = 0; r < RPW; r++) {
                u64 t2 = ffma2(rz2[r], zw.x, zw.y);
                t2 = ffma2(ry2[r], ab.y, t2);
                t2 = ffma2(rx2[r], ab.x, t2);
                float lo, hi; unpk(t2, lo, hi);
                mlo[r] = fmaxf(mlo[r], lo);
                mhi[r] = fmaxf(mhi[r], hi);
            }
        }
        float mt[RPW];
#pragma unroll
        for (int r = 0; r < RPW; r++) mt[r] = fmaxf(mlo[r], mhi[r]);
#pragma unroll
        for (int off = 16; off; off >>= 1)
#pragma unroll
            for (int r = 0; r < RPW; r++)
                mt[r] = fmaxf(mt[r], __shfl_xor_sync(0xffffffffu, mt[r], off));
        u64 sb2[RPW], mkb[RPW];
#pragma unroll
        for (int r = 0; r < RPW; r++) { mkb[r] = dup2(-mt[r] * kk); sb2[r] = 0; }
        for (int k = lane; k < NPAIR; k += 32) {
            ulonglong2 ab = sA[k];
            ulonglong2 zw = sB[k];
#pragma unroll
            for (int r = 0; r < RPW; r++) {
                u64 t2 = ffma2(rz2[r], zw.x, zw.y);
                t2 = ffma2(ry2[r], ab.y, t2);
                t2 = ffma2(rx2[r], ab.x, t2);
                sb2[r] = fadd2(sb2[r], ex2pair(ffma2(t2, kk2, mkb[r])));
            }
        }
        float sn[RPW];
#pragma unroll
        for (int r = 0; r < RPW; r++) { float lo, hi; unpk(sb2[r], lo, hi); sn[r] = lo + hi; }
#pragma unroll
        for (int off = 16; off; off >>= 1)
#pragma unroll
            for (int r = 0; r < RPW; r++)
                sn[r] += __shfl_xor_sync(0xffffffffu, sn[r], off);
#pragma unroll
        for (int r = 0; r < RPW; r++)
            if ((badmask >> r) & 1u) { s[r] = sn[r]; m_used[r] = mt[r]; }
    }

    if (lane < RPW) {
        int r = lane;
        int row = row0 + r;
        float rww = rows[row].w;
        float sm = rww - m_used[r] - eps * (lg2(s[r]) * LN2);
        outp[row] = avg ? 0.5f * (rowold[row] + sm) : sm;
        mprev[row] = rww - sm;
    }
}

__global__ void reduce_kernel(int buf, float* __restrict__ out) {
    __shared__ float red[256];
    float acc = 0.f;
    for (int i = threadIdx.x; i < NTOT; i += 256) {
        acc += (d_pots[buf][0][i] - d_pots[buf][2][i])
             + (d_pots[buf][1][i] - d_pots[buf][3][i]);
    }
    red[threadIdx.x] = acc;
    __syncthreads();
    for (int off = 128; off; off >>= 1) {
        if (threadIdx.x < off) red[threadIdx.x] += red[threadIdx.x + off];
        __syncthreads();
    }
    if (threadIdx.x == 0) out[0] = red[0] / (float)NTOT;
}

extern "C" void kernel_launch(void* const* d_in, const int* in_sizes, int n_in,
                              void* d_out, int out_size) {
    const float* p1 = (const float*)d_in[0];
    const float* p2 = (const float*)d_in[1];
    float* out = (float*)d_out;

    float eps[128]; int n = 0;
    double sc = 8.0;
    while (sc > 0.01 && n < 120) { float f = (float)sc; eps[n++] = f * f; sc *= 0.9; }
    { float f = 0.01f; eps[n++] = f * f; }

    prep_kernel<<<dim3(B, 2), 256>>>(p1, p2);

    int inbuf = 0;
    dim3 grid(NPTS / RPB, B, 4);
    for (int k = 0; k < n; k++) {
        int screen = (eps[k] <= 0.05f) ? 1 : 0;
        iter_kernel<<<grid, TPB>>>(eps[k], inbuf, 1, 0, screen);
        inbuf ^= 1;
    }
    iter_kernel<<<grid, TPB>>>(eps[n - 1], inbuf, 0, 1, 0);
    reduce_kernel<<<1, 256>>>(inbuf ^ 1, out);
}

// round 14
// speedup vs baseline: 1.0523x; 1.0104x over previous
#include <cuda_runtime.h>

#define B 8
#define NPTS 2048
#define NPAIR (NPTS/2)
#define NTOT (B*NPTS)
#define LOGW 7.6246189861593985f   /* ln(2048) */
#define LOG2E 1.4426950408889634f
#define LN2 0.6931471805599453f
#define EXP2SCALE 8388608.0f       /* 2^23 */
#define SCHBIAS 1064986823.0f      /* (127 - 0.043677) * 2^23 */

typedef unsigned long long u64;

__device__ float4 d_X4[NTOT];              // per-row coords (x,y,z, 0.5|p|^2)
__device__ float4 d_Y4[NTOT];
__device__ float4 d_cA[2][NTOT/2];         // pair-packed cols: (x0,x1,y0,y1)
__device__ float4 d_cB[2][NTOT/2];         // pair-packed cols: (z0,z1,-w0,-w1)
__device__ float d_pots[2][4][NTOT];       // [buffer][f,g,fx,gy][b*N+i]
__device__ float d_mprev[4][NTOT];         // row-max estimate (= w - softmin_raw)

__device__ __forceinline__ float lg2(float x){ float r; asm("lg2.approx.f32 %0, %1;":"=f"(r):"f"(x)); return r; }
__device__ __forceinline__ u64 dup2(float x){ u64 r; asm("mov.b64 %0, {%1, %1};":"=l"(r):"f"(x)); return r; }
__device__ __forceinline__ u64 ffma2(u64 a, u64 b, u64 c){ u64 r; asm("fma.rn.f32x2 %0, %1, %2, %3;":"=l"(r):"l"(a),"l"(b),"l"(c)); return r; }
__device__ __forceinline__ u64 fadd2(u64 a, u64 b){ u64 r; asm("add.rn.f32x2 %0, %1, %2;":"=l"(r):"l"(a),"l"(b)); return r; }
__device__ __forceinline__ void unpk(u64 v, float& lo, float& hi){ asm("mov.b64 {%0, %1}, %2;":"=f"(lo),"=f"(hi):"l"(v)); }
// Saturating Schraudolph: bitsf holds the target float's bit pattern as a float.
// cvt.rni.u32.f32 saturates negatives to 0 (=+0.0f: exact flush of underflow)
// and huge values to 0xFFFFFFFF (=NaN: trips the badmask fallback).
__device__ __forceinline__ u64 schexp(u64 b2){
    u64 r;
    asm("{\n\t.reg .f32 l, h;\n\t.reg .b32 il, ih;\n\t"
        "mov.b64 {l, h}, %1;\n\t"
        "cvt.rni.u32.f32 il, l;\n\t"
        "cvt.rni.u32.f32 ih, h;\n\t"
        "mov.b64 %0, {il, ih};\n\t}"
        : "=l"(r) : "l"(b2));
    return r;
}
__device__ __forceinline__ u64 ex2pair(u64 a){
    u64 r;
    asm("{\n\t.reg .f32 lo, hi, el, eh;\n\t"
        "mov.b64 {lo, hi}, %1;\n\t"
        "ex2.approx.ftz.f32 el, lo;\n\t"
        "ex2.approx.ftz.f32 eh, hi;\n\t"
        "mov.b64 %0, {el, eh};\n\t}"
        : "=l"(r) : "l"(a));
    return r;
}

__global__ void prep_kernel(const float* __restrict__ p1, const float* __restrict__ p2) {
    int i = blockIdx.x * blockDim.x + threadIdx.x;   // pair index
    if (i >= NTOT/2) return;
    int j0 = 2*i, j1 = 2*i + 1;
    float x0 = p1[3*j0], y0 = p1[3*j0+1], z0 = p1[3*j0+2];
    float x1 = p1[3*j1], y1 = p1[3*j1+1], z1 = p1[3*j1+2];
    float w0 = 0.5f*(x0*x0+y0*y0+z0*z0), w1 = 0.5f*(x1*x1+y1*y1+z1*z1);
    d_X4[j0] = make_float4(x0,y0,z0,w0);
    d_X4[j1] = make_float4(x1,y1,z1,w1);
    d_cA[0][i] = make_float4(x0,x1,y0,y1);
    d_cB[0][i] = make_float4(z0,z1,-w0,-w1);
    x0 = p2[3*j0]; y0 = p2[3*j0+1]; z0 = p2[3*j0+2];
    x1 = p2[3*j1]; y1 = p2[3*j1+1]; z1 = p2[3*j1+2];
    w0 = 0.5f*(x0*x0+y0*y0+z0*z0); w1 = 0.5f*(x1*x1+y1*y1+z1*z1);
    d_Y4[j0] = make_float4(x0,y0,z0,w0);
    d_Y4[j1] = make_float4(x1,y1,z1,w1);
    d_cA[1][i] = make_float4(x0,x1,y0,y1);
    d_cB[1][i] = make_float4(z0,z1,-w0,-w1);
    d_pots[0][0][j0]=0.f; d_pots[0][1][j0]=0.f; d_pots[0][2][j0]=0.f; d_pots[0][3][j0]=0.f;
    d_pots[0][0][j1]=0.f; d_pots[0][1][j1]=0.f; d_pots[0][2][j1]=0.f; d_pots[0][3][j1]=0.f;
    d_mprev[0][j0]=0.f; d_mprev[1][j0]=0.f; d_mprev[2][j0]=0.f; d_mprev[3][j0]=0.f;
    d_mprev[0][j1]=0.f; d_mprev[1][j1]=0.f; d_mprev[2][j1]=0.f; d_mprev[3][j1]=0.f;
}

#define RPW 4
#define WARPS 8
#define TPB (WARPS*32)  // 256
#define RPB (RPW*WARPS) // 32

// Single-pass softmin with prev-iteration max estimate.
//   t_ij = (h_j - 0.5|y_j|^2 - eps*logw) + x_i . y_j
//   softmin_i = 0.5|x_i|^2 - m - eps*ln( sum_j exp((t_ij - m)/eps) )
// exact=0: saturating-Schraudolph exp on the fma pipe (ZERO MUFU in the loop);
// exact=1: f32 MUFU exp (final extrapolation).
__global__ __launch_bounds__(TPB, 4) void iter_kernel(float eps, int inbuf, int avg, int exact) {
    __shared__ float4 shA[NPAIR];   // (x0,x1,y0,y1)
    __shared__ float4 shB[NPAIR];   // (z0,z1,w'0,w'1)
    int task = blockIdx.z, b = blockIdx.y;
    int ob = inbuf ^ 1;
    const float4* rows; const float4* cA; const float4* cB;
    const float* colpot; const float* rowold; float* outp;
    if (task == 0)      { rows = d_X4; cA = d_cA[1]; cB = d_cB[1]; colpot = d_pots[inbuf][1]; rowold = d_pots[inbuf][0]; outp = d_pots[ob][0]; }
    else if (task == 1) { rows = d_Y4; cA = d_cA[0]; cB = d_cB[0]; colpot = d_pots[inbuf][0]; rowold = d_pots[inbuf][1]; outp = d_pots[ob][1]; }
    else if (task == 2) { rows = d_X4; cA = d_cA[0]; cB = d_cB[0]; colpot = d_pots[inbuf][2]; rowold = d_pots[inbuf][2]; outp = d_pots[ob][2]; }
    else                { rows = d_Y4; cA = d_cA[1]; cB = d_cB[1]; colpot = d_pots[inbuf][3]; rowold = d_pots[inbuf][3]; outp = d_pots[ob][3]; }
    float* mprev = d_mprev[task] + b*NPTS;
    rows += b*NPTS; cA += b*NPAIR; cB += b*NPAIR; colpot += b*NPTS; rowold += b*NPTS; outp += b*NPTS;

    float eps_logw = eps * LOGW;
    for (int k = threadIdx.x; k < NPAIR; k += TPB) {
        shA[k] = cA[k];
        float4 zb = cB[k];
        float p0 = colpot[2*k], p1 = colpot[2*k+1];
        shB[k] = make_float4(zb.x, zb.y, p0 + zb.z - eps_logw, p1 + zb.w - eps_logw);
    }
    __syncthreads();

    int warp = threadIdx.x >> 5, lane = threadIdx.x & 31;
    int row0 = blockIdx.x * RPB + warp * RPW;

    float kk = LOG2E / eps;
    float kks = kk * EXP2SCALE;       // scale straight to exponent-bit units

    u64 rx2[RPW], ry2[RPW], rz2[RPW], mk2[RPW];
    u64 s2[RPW];
#pragma unroll
    for (int r = 0; r < RPW; r++) {
        float4 xr = rows[row0 + r];
        rx2[r] = dup2(xr.x); ry2[r] = dup2(xr.y); rz2[r] = dup2(xr.z);
        float me = mprev[row0 + r];
        // exact path uses -m*kk; schraudolph path uses bias - m*kk*2^23
        mk2[r] = exact ? dup2(-me * kk) : dup2(SCHBIAS - me * kks);
        s2[r] = 0;
    }
    u64 kk2 = exact ? dup2(kk) : dup2(kks);

    const ulonglong2* sA = (const ulonglong2*)shA;
    const ulonglong2* sB = (const ulonglong2*)shB;

    if (!exact) {
        // Schraudolph path: all math on fma pipe + 2 cvt; no MUFU
#pragma unroll 4
        for (int k = lane; k < NPAIR; k += 32) {
            ulonglong2 ab = sA[k];        // x-pair, y-pair
            ulonglong2 zw = sB[k];        // z-pair, w'-pair
#pragma unroll
            for (int r = 0; r < RPW; r++) {
                u64 t2 = ffma2(rz2[r], zw.x, zw.y);
                t2 = ffma2(ry2[r], ab.y, t2);
                t2 = ffma2(rx2[r], ab.x, t2);
                u64 b2 = ffma2(t2, kk2, mk2[r]);   // float bit pattern as float
                s2[r] = fadd2(s2[r], schexp(b2));
            }
        }
    } else {
        // exact f32 MUFU exp path (final extrapolation)
#pragma unroll 4
        for (int k = lane; k < NPAIR; k += 32) {
            ulonglong2 ab = sA[k];
            ulonglong2 zw = sB[k];
#pragma unroll
            for (int r = 0; r < RPW; r++) {
                u64 t2 = ffma2(rz2[r], zw.x, zw.y);
                t2 = ffma2(ry2[r], ab.y, t2);
                t2 = ffma2(rx2[r], ab.x, t2);
                s2[r] = fadd2(s2[r], ex2pair(ffma2(t2, kk2, mk2[r])));
            }
        }
    }

    float s[RPW];
#pragma unroll
    for (int r = 0; r < RPW; r++) { float lo, hi; unpk(s2[r], lo, hi); s[r] = lo + hi; }
#pragma unroll
    for (int off = 16; off; off >>= 1)
#pragma unroll
        for (int r = 0; r < RPW; r++)
            s[r] += __shfl_xor_sync(0xffffffffu, s[r], off);

    float m_used[RPW];
#pragma unroll
    for (int r = 0; r < RPW; r++) m_used[r] = mprev[row0 + r];

    float kkx = LOG2E / eps;
    // safety net: NaN/overflow/underflow in s -> recompute max + exact resum
    unsigned badmask = 0;
#pragma unroll
    for (int r = 0; r < RPW; r++)
        if (!(s[r] >= 1e-12f && s[r] <= 1e30f)) badmask |= 1u << r;
    if (__any_sync(0xffffffffu, badmask != 0)) {
        u64 kkb = dup2(kkx);
        float mlo[RPW], mhi[RPW];
#pragma unroll
        for (int r = 0; r < RPW; r++) { mlo[r] = -3.4e38f; mhi[r] = -3.4e38f; }
        for (int k = lane; k < NPAIR; k += 32) {
            ulonglong2 ab = sA[k];
            ulonglong2 zw = sB[k];
#pragma unroll
            for (int r = 0; r < RPW; r++) {
                u64 t2 = ffma2(rz2[r], zw.x, zw.y);
                t2 = ffma2(ry2[r], ab.y, t2);
                t2 = ffma2(rx2[r], ab.x, t2);
                float lo, hi; unpk(t2, lo, hi);
                mlo[r] = fmaxf(mlo[r], lo);
                mhi[r] = fmaxf(mhi[r], hi);
            }
        }
        float mt[RPW];
#pragma unroll
        for (int r = 0; r < RPW; r++) mt[r] = fmaxf(mlo[r], mhi[r]);
#pragma unroll
        for (int off = 16; off; off >>= 1)
#pragma unroll
            for (int r = 0; r < RPW; r++)
                mt[r] = fmaxf(mt[r], __shfl_xor_sync(0xffffffffu, mt[r], off));
        u64 sb2[RPW], mkb[RPW];
#pragma unroll
        for (int r = 0; r < RPW; r++) { mkb[r] = dup2(-mt[r] * kkx); sb2[r] = 0; }
        for (int k = lane; k < NPAIR; k += 32) {
            ulonglong2 ab = sA[k];
            ulonglong2 zw = sB[k];
#pragma unroll
            for (int r = 0; r < RPW; r++) {
                u64 t2 = ffma2(rz2[r], zw.x, zw.y);
                t2 = ffma2(ry2[r], ab.y, t2);
                t2 = ffma2(rx2[r], ab.x, t2);
                sb2[r] = fadd2(sb2[r], ex2pair(ffma2(t2, kkb, mkb[r])));
            }
        }
        float sn[RPW];
#pragma unroll
        for (int r = 0; r < RPW; r++) { float lo, hi; unpk(sb2[r], lo, hi); sn[r] = lo + hi; }
#pragma unroll
        for (int off = 16; off; off >>= 1)
#pragma unroll
            for (int r = 0; r < RPW; r++)
                sn[r] += __shfl_xor_sync(0xffffffffu, sn[r], off);
#pragma unroll
        for (int r = 0; r < RPW; r++)
            if ((badmask >> r) & 1u) { s[r] = sn[r]; m_used[r] = mt[r]; }
    }

    if (lane < RPW) {
        int r = lane;
        int row = row0 + r;
        float rww = rows[row].w;
        float sm = rww - m_used[r] - eps * (lg2(s[r]) * LN2);
        outp[row] = avg ? 0.5f * (rowold[row] + sm) : sm;
        mprev[row] = rww - sm;
    }
}

__global__ void reduce_kernel(int buf, float* __restrict__ out) {
    __shared__ float red[256];
    float acc = 0.f;
    for (int i = threadIdx.x; i < NTOT; i += 256) {
        acc += (d_pots[buf][0][i] - d_pots[buf][2][i])
             + (d_pots[buf][1][i] - d_pots[buf][3][i]);
    }
    red[threadIdx.x] = acc;
    __syncthreads();
    for (int off = 128; off; off >>= 1) {
        if (threadIdx.x < off) red[threadIdx.x] += red[threadIdx.x + off];
        __syncthreads();
    }
    if (threadIdx.x == 0) out[0] = red[0] / (float)NTOT;
}

extern "C" void kernel_launch(void* const* d_in, const int* in_sizes, int n_in,
                              void* d_out, int out_size) {
    const float* p1 = (const float*)d_in[0];
    const float* p2 = (const float*)d_in[1];
    float* out = (float*)d_out;

    float eps[128]; int n = 0;
    double sc = 8.0;
    while (sc > 0.01 && n < 120) { float f = (float)sc; eps[n++] = f * f; sc *= 0.9; }
    { float f = 0.01f; eps[n++] = f * f; }

    prep_kernel<<<(NTOT/2 + 255) / 256, 256>>>(p1, p2);

    int inbuf = 0;
    dim3 grid(NPTS / RPB, B, 4);
    for (int k = 0; k < n; k++) {
        iter_kernel<<<grid, TPB>>>(eps[k], inbuf, 1, 0);
        inbuf ^= 1;
    }
    // final extrapolation at target eps: exact f32 exp, no averaging
    iter_kernel<<<grid, TPB>>>(eps[n - 1], inbuf, 0, 1);
    reduce_kernel<<<1, 256>>>(inbuf ^ 1, out);
}